// round 15
// baseline (speedup 1.0000x reference)
#include <cuda_runtime.h>
#include <cuda_bf16.h>
#include <stdint.h>
#include <math.h>

// Problem constants
#define NB 64
#define NH 1024
#define NR 196
#define NL 512
#define NK 512
#define NBR (NB * NR)   // 12544 = 49 * 256 (exact M tiling!)

// ---------------- scratch (device globals; no allocation allowed) ----------
__device__ __nv_bfloat16 g_Vt   [(size_t)NB*NR*NH];
__device__ __nv_bfloat16 g_Qbf  [(size_t)NB*NL*NH];
__device__ __nv_bfloat16 g_Wb   [(size_t)NH*NH];
__device__ __nv_bfloat16 g_Wv   [(size_t)NK*NH];
__device__ __nv_bfloat16 g_Wq   [(size_t)NK*NH];
__device__ float         g_whv  [NK];
__device__ float         g_whq  [NK];
__device__ __nv_bfloat16 g_WbVt [(size_t)NBR*NH];      // [B*R][H]
__device__ __nv_bfloat16 g_C    [(size_t)NB*NL*NR];    // [B][L][R]
__device__ __nv_bfloat16 g_WvV2 [(size_t)NK*NBR];      // [K][B*R]  (ld = 12544)
__device__ __nv_bfloat16 g_WqQt [(size_t)NB*NK*NL];    // [B][K][L]
__device__ __nv_bfloat16 g_Hv   [(size_t)NB*NK*NR];    // [B][K][R]
__device__ __nv_bfloat16 g_Hq   [(size_t)NB*NK*NL];    // [B][K][L]
__device__ __nv_bfloat16 g_av   [NB*NR];
__device__ __nv_bfloat16 g_maq  [NB*NL];
__device__ int           g_len  [NB];

// ---------------- small helpers --------------------------------------------
__device__ __forceinline__ float rnd_bf(float x) {
    return __bfloat162float(__float2bfloat16(x));
}

__device__ __forceinline__ float blk_max(float v, float* red, int tid, int nt) {
    red[tid] = v; __syncthreads();
    for (int o = nt >> 1; o > 0; o >>= 1) {
        if (tid < o) red[tid] = fmaxf(red[tid], red[tid + o]);
        __syncthreads();
    }
    float r = red[0]; __syncthreads();
    return r;
}
__device__ __forceinline__ float blk_sum(float v, float* red, int tid, int nt) {
    red[tid] = v; __syncthreads();
    for (int o = nt >> 1; o > 0; o >>= 1) {
        if (tid < o) red[tid] += red[tid + o];
        __syncthreads();
    }
    float r = red[0]; __syncthreads();
    return r;
}

// ---------------- conversions ----------------------------------------------
__global__ void k_zero_f32(float* __restrict__ dst, long n) {
    long i = (long)blockIdx.x * blockDim.x + threadIdx.x;
    long st = (long)gridDim.x * blockDim.x;
    for (; i < n; i += st) dst[i] = 0.f;
}

__global__ void k_f32_to_bf16_v4(const float4* __restrict__ src,
                                 uint2* __restrict__ dst, long n4) {
    long i = (long)blockIdx.x * blockDim.x + threadIdx.x;
    long st = (long)gridDim.x * blockDim.x;
    for (; i < n4; i += st) {
        float4 v = src[i];
        __nv_bfloat16 b0 = __float2bfloat16(v.x), b1 = __float2bfloat16(v.y);
        __nv_bfloat16 b2 = __float2bfloat16(v.z), b3 = __float2bfloat16(v.w);
        uint2 o;
        o.x = (uint32_t)*reinterpret_cast<uint16_t*>(&b0) |
              ((uint32_t)*reinterpret_cast<uint16_t*>(&b1) << 16);
        o.y = (uint32_t)*reinterpret_cast<uint16_t*>(&b2) |
              ((uint32_t)*reinterpret_cast<uint16_t*>(&b3) << 16);
        dst[i] = o;
    }
}

__global__ void k_round_w(const float* __restrict__ src, float* __restrict__ dst, int n) {
    int i = blockIdx.x * blockDim.x + threadIdx.x;
    if (i < n) dst[i] = rnd_bf(src[i]);
}

// convert V [B,H,R] f32 -> transposed bf16 g_Vt [B,R,H]
__global__ void k_convV(const float* __restrict__ V) {
    __shared__ float tile[32][33];
    int b = blockIdx.z;
    int r0 = blockIdx.x * 32, h0 = blockIdx.y * 32;
    int tx = threadIdx.x, ty = threadIdx.y;
    const float* Vb = V + (size_t)b * NH * NR;
#pragma unroll
    for (int i = 0; i < 4; i++) {
        int h = h0 + ty + i * 8, r = r0 + tx;
        float v = 0.f;
        if (h < NH && r < NR) v = Vb[(size_t)h * NR + r];
        tile[ty + i * 8][tx] = v;
    }
    __syncthreads();
#pragma unroll
    for (int i = 0; i < 4; i++) {
        int r = r0 + ty + i * 8, h = h0 + tx;
        if (r < NR && h < NH)
            g_Vt[(size_t)b * NR * NH + (size_t)r * NH + h] = __float2bfloat16(tile[tx][ty + i * 8]);
    }
}

// normalize Q_lengths (handles both int32 and int64 storage)
__global__ void k_len(const void* __restrict__ p) {
    const int* pi = (const int*)p;
    __shared__ int is64;
    if (threadIdx.x == 0) {
        int flag = 1;
        for (int i = 1; i < 64; i += 2)
            if (pi[i] != 0) { flag = 0; break; }
        is64 = flag;
    }
    __syncthreads();
    int i = threadIdx.x;
    if (i < NB) g_len[i] = is64 ? pi[2 * i] : pi[i];
}

// ---------------- fast SIMT GEMM (256x128 tile, GBK=32, 256 thr, 16x8/thr) --
// C[M,N] = A[M,K] * op(B), op = B[N,K]^T (BNN=0) or B[K,N] (BNN=1).
// Sequential ascending-k per output element, single f32 accumulator
// (FFMA2 = elementwise IEEE f32 FMA; bit-identical to scalar chains).
// Thread: 16 rows (8 M-pairs) x 8 cols {tx*4+0..3} U {64+tx*4+0..3}.
// EPI==0: C = bf16(acc)
// EPI==1: C = bf16(tanh(bf16(bf16(acc) + Add[M,N])))
#define GBM 256
#define GBN 128
#define GBK 32
#define GTHREADS 256

// load 8 consecutive bf16 P[row][col..col+7] (leading dim ld) into 4 uint32
__device__ __forceinline__ void ld8g(const __nv_bfloat16* __restrict__ P,
                                     int row, int col, int nrow, int ncol,
                                     int ld, uint32_t r[4]) {
    if (row < nrow && col + 8 <= ncol) {
        const uint2* p = reinterpret_cast<const uint2*>(P + (size_t)row * ld + col);
        uint2 a = p[0], b = p[1];
        r[0] = a.x; r[1] = a.y; r[2] = b.x; r[3] = b.y;
    } else {
        uint16_t t[8];
#pragma unroll
        for (int j = 0; j < 8; j++) {
            __nv_bfloat16 v = (row < nrow && col + j < ncol)
                              ? P[(size_t)row * ld + col + j] : __nv_bfloat16(0.f);
            t[j] = *reinterpret_cast<uint16_t*>(&v);
        }
#pragma unroll
        for (int j = 0; j < 4; j++) r[j] = (uint32_t)t[2 * j] | ((uint32_t)t[2 * j + 1] << 16);
    }
}

template<int EPI, int BNN>
__global__ __launch_bounds__(GTHREADS, 1) void k_fgemm(
    const __nv_bfloat16* __restrict__ A, int lda, long strA,
    const __nv_bfloat16* __restrict__ Bm, int ldb, long strB,
    __nv_bfloat16* __restrict__ C, int ldc, long strC,
    const __nv_bfloat16* __restrict__ Add, int ldadd, long strAdd,
    int M, int N, int Kd)
{
    __shared__ float As[GBK][GBM];   // 32 KB
    __shared__ float Bs[GBK][GBN];   // 16 KB  (total = 48 KB exactly)

    int bz = blockIdx.z;
    A += (size_t)bz * strA;
    Bm += (size_t)bz * strB;
    C += (size_t)bz * strC;
    if (EPI) Add += (size_t)bz * strAdd;

    int m0 = blockIdx.y * GBM, n0 = blockIdx.x * GBN;
    int tid = threadIdx.x;
    int rowA = tid;                   // A loader: one row, 32 k-cols (4 x ld8g)
    int rowB = tid >> 1;              // NT B loader: 0..127
    int c16 = (tid & 1) * 16;         // NT B loader col offset (2 x ld8g)
    int kkB = tid >> 4;               // NN: k rows kkB and kkB+16
    int n8B = (tid & 15) * 8;         // NN
    int tx = tid & 15, ty = tid >> 4; // 16x16 grid, 16x8 per thread

    uint64_t acc2[8][8];
#pragma unroll
    for (int p = 0; p < 8; p++)
#pragma unroll
        for (int j = 0; j < 8; j++) acc2[p][j] = 0ull;

    int nk = (Kd + GBK - 1) / GBK;
    uint32_t ra[4][4], rb[2][4];

    auto prefetch = [&](int gk) {
#pragma unroll
        for (int s = 0; s < 4; s++)
            ld8g(A, m0 + rowA, gk + s * 8, M, Kd, lda, ra[s]);
        if (BNN) {
#pragma unroll
            for (int s = 0; s < 2; s++)
                ld8g(Bm, gk + kkB + s * 16, n0 + n8B, Kd, N, ldb, rb[s]);
        } else {
#pragma unroll
            for (int s = 0; s < 2; s++)
                ld8g(Bm, n0 + rowB, gk + c16 + s * 8, N, Kd, ldb, rb[s]);
        }
    };

    prefetch(0);

    for (int kt = 0; kt < nk; ++kt) {
        // deposit prefetched tile (bf16->f32 exact bit shift)
#pragma unroll
        for (int s = 0; s < 4; s++)
#pragma unroll
            for (int j = 0; j < 4; j++) {
                As[s * 8 + 2 * j][rowA]     = __uint_as_float(ra[s][j] << 16);
                As[s * 8 + 2 * j + 1][rowA] = __uint_as_float(ra[s][j] & 0xffff0000u);
            }
        if (BNN) {
#pragma unroll
            for (int s = 0; s < 2; s++)
#pragma unroll
                for (int j = 0; j < 4; j++) {
                    float2 w;
                    w.x = __uint_as_float(rb[s][j] << 16);
                    w.y = __uint_as_float(rb[s][j] & 0xffff0000u);
                    *reinterpret_cast<float2*>(&Bs[kkB + s * 16][n8B + 2 * j]) = w;
                }
        } else {
#pragma unroll
            for (int s = 0; s < 2; s++)
#pragma unroll
                for (int j = 0; j < 4; j++) {
                    Bs[c16 + s * 8 + 2 * j][rowB]     = __uint_as_float(rb[s][j] << 16);
                    Bs[c16 + s * 8 + 2 * j + 1][rowB] = __uint_as_float(rb[s][j] & 0xffff0000u);
                }
        }
        __syncthreads();

        if (kt + 1 < nk) prefetch((kt + 1) * GBK);

#pragma unroll
        for (int k = 0; k < GBK; k++) {
            const ulonglong2* pa = reinterpret_cast<const ulonglong2*>(&As[k][ty * 16]);
            ulonglong2 aa = pa[0], ab = pa[1], ac = pa[2], ad = pa[3];
            uint64_t a2[8] = {aa.x, aa.y, ab.x, ab.y, ac.x, ac.y, ad.x, ad.y};
            // conflict-free B fragment: cols tx*4..+3 and 64+tx*4..+3
            float4 b0 = *reinterpret_cast<const float4*>(&Bs[k][tx * 4]);
            float4 b1 = *reinterpret_cast<const float4*>(&Bs[k][64 + tx * 4]);
            float bv[8] = {b0.x, b0.y, b0.z, b0.w, b1.x, b1.y, b1.z, b1.w};
            uint64_t b2[8];
#pragma unroll
            for (int j = 0; j < 8; j++)
                asm("mov.b64 %0, {%1, %1};" : "=l"(b2[j]) : "f"(bv[j]));
#pragma unroll
            for (int p = 0; p < 8; p++)
#pragma unroll
                for (int j = 0; j < 8; j++)
                    asm("fma.rn.f32x2 %0, %1, %2, %0;"
                        : "+l"(acc2[p][j]) : "l"(a2[p]), "l"(b2[j]));
        }
        __syncthreads();
    }

    // epilogue: 16 rows (8 pairs) x two 4-col groups
#pragma unroll
    for (int p = 0; p < 8; p++) {
#pragma unroll
        for (int half = 0; half < 2; half++) {
            int r = m0 + ty * 16 + 2 * p + half;
            if (r >= M) continue;
#pragma unroll
            for (int g = 0; g < 2; g++) {
                int c0 = n0 + g * 64 + tx * 4;
                float accv[4];
#pragma unroll
                for (int j = 0; j < 4; j++) {
                    uint64_t v = acc2[p][g * 4 + j];
                    accv[j] = __uint_as_float(half ? (uint32_t)(v >> 32) : (uint32_t)v);
                }
                uint16_t outp[4];
                if (EPI == 0) {
#pragma unroll
                    for (int j = 0; j < 4; j++) {
                        __nv_bfloat16 v = __float2bfloat16(accv[j]);
                        outp[j] = *reinterpret_cast<uint16_t*>(&v);
                    }
                } else {
                    float addv[4];
                    if (c0 + 4 <= N) {
                        uint2 a = *reinterpret_cast<const uint2*>(Add + (size_t)r * ldadd + c0);
                        addv[0] = __uint_as_float(a.x << 16);
                        addv[1] = __uint_as_float(a.x & 0xffff0000u);
                        addv[2] = __uint_as_float(a.y << 16);
                        addv[3] = __uint_as_float(a.y & 0xffff0000u);
                    } else {
#pragma unroll
                        for (int j = 0; j < 4; j++)
                            addv[j] = (c0 + j < N)
                                      ? __bfloat162float(Add[(size_t)r * ldadd + c0 + j]) : 0.f;
                    }
#pragma unroll
                    for (int j = 0; j < 4; j++) {
                        float s = rnd_bf(accv[j]) + addv[j];
                        __nv_bfloat16 v = __float2bfloat16(tanhf(rnd_bf(s)));
                        outp[j] = *reinterpret_cast<uint16_t*>(&v);
                    }
                }
                if (c0 + 4 <= N) {
                    uint2 w;
                    w.x = (uint32_t)outp[0] | ((uint32_t)outp[1] << 16);
                    w.y = (uint32_t)outp[2] | ((uint32_t)outp[3] << 16);
                    *reinterpret_cast<uint2*>(C + (size_t)r * ldc + c0) = w;
                } else {
#pragma unroll
                    for (int j = 0; j < 4; j++)
                        if (c0 + j < N)
                            *reinterpret_cast<uint16_t*>(C + (size_t)r * ldc + c0 + j) = outp[j];
                }
            }
        }
    }
}

// ---------------- s_v reduce + bf16-emulated softmax (a_v) -> f32 out -------
__global__ void k_sv_softmax(float* __restrict__ out) {
    int b = blockIdx.x;
    __shared__ float wsm[NK];
    __shared__ float red[256];
    int tid = threadIdx.x;
    for (int i = tid; i < NK; i += 256) wsm[i] = g_whv[i];
    __syncthreads();
    const __nv_bfloat16* Hv = g_Hv + (size_t)b * NK * NR;
    float s = -INFINITY;
    int r = tid;
    if (r < NR) {
        float acc = 0.f;
        for (int k = 0; k < NK; k++)
            acc = fmaf(wsm[k], __bfloat162float(Hv[(size_t)k * NR + r]), acc);
        s = rnd_bf(acc);
    }
    float mx = blk_max(s, red, tid, 256);
    float e = 0.f;
    if (r < NR) e = rnd_bf(expf(rnd_bf(s - mx)));
    float sum = rnd_bf(blk_sum(e, red, tid, 256));
    if (r < NR) {
        __nv_bfloat16 av = __float2bfloat16(e / sum);
        g_av[b * NR + r] = av;
        out[b * NR + r] = __bfloat162float(av);
    }
}

// ---------------- s_q reduce + bf16 softmax + f32 masked softmax ------------
__global__ void k_sq_softmax(float* __restrict__ out) {
    int b = blockIdx.x;
    __shared__ float wsm[NK];
    __shared__ float red[512];
    int tid = threadIdx.x;  // 512
    for (int i = tid; i < NK; i += 512) wsm[i] = g_whq[i];
    __syncthreads();
    const __nv_bfloat16* Hq = g_Hq + (size_t)b * NK * NL;
    float acc = 0.f;
    for (int k = 0; k < NK; k++)
        acc = fmaf(wsm[k], __bfloat162float(Hq[(size_t)k * NL + tid]), acc);
    float s = rnd_bf(acc);
    float mx = blk_max(s, red, tid, 512);
    float e = rnd_bf(expf(rnd_bf(s - mx)));
    float sum = rnd_bf(blk_sum(e, red, tid, 512));
    float aqf = rnd_bf(e / sum);
    int len = g_len[b];
    float sc = (tid < len) ? aqf : -INFINITY;
    float m2 = blk_max(sc, red, tid, 512);
    float e2 = (tid < len) ? expf(sc - m2) : 0.f;
    float s2 = blk_sum(e2, red, tid, 512);
    __nv_bfloat16 mq = __float2bfloat16(e2 / s2);
    g_maq[b * NL + tid] = mq;
    out[b * NL + tid] = __bfloat162float(mq);
}

// ---------------- v = V @ a_v  (reads Vt coalesced, sequential r) -----------
__global__ void k_v(float* __restrict__ out) {
    int b = blockIdx.y;
    int h = blockIdx.x * 256 + threadIdx.x;
    __shared__ float av[NR];
    for (int i = threadIdx.x; i < NR; i += 256)
        av[i] = __bfloat162float(g_av[b * NR + i]);
    __syncthreads();
    const __nv_bfloat16* Vtb = g_Vt + (size_t)b * NR * NH;
    float acc = 0.f;
    for (int r = 0; r < NR; r++)
        acc = fmaf(av[r], __bfloat162float(Vtb[(size_t)r * NH + h]), acc);
    out[b * NH + h] = rnd_bf(acc);
}

// ---------------- q = Q^T @ masked_a_q ---------------------------------------
__global__ void k_q(float* __restrict__ out) {
    int b = blockIdx.y;
    int h = blockIdx.x * 256 + threadIdx.x;
    __shared__ float aq[NL];
    for (int i = threadIdx.x; i < NL; i += 256)
        aq[i] = __bfloat162float(g_maq[b * NL + i]);
    __syncthreads();
    const __nv_bfloat16* Qb = g_Qbf + (size_t)b * NL * NH;
    float acc = 0.f;
    for (int l = 0; l < NL; l++)
        acc = fmaf(aq[l], __bfloat162float(Qb[(size_t)l * NH + h]), acc);
    out[b * NH + h] = rnd_bf(acc);
}

// ---------------- host ---------------------------------------------------------
extern "C" void kernel_launch(void* const* d_in, const int* in_sizes, int n_in,
                              void* d_out, int out_size) {
    // identify inputs by element count
    int iV = -1, iQ = -1, iLen = -1, iWb = -1;
    int i524[2] = {-1, -1}, n524 = 0;
    int i512[2] = {-1, -1}, n512 = 0;
    for (int i = 0; i < n_in; i++) {
        long s = in_sizes[i];
        if      (s == 12845056) iV = i;
        else if (s == 33554432) iQ = i;
        else if (s == 64)       iLen = i;
        else if (s == 1048576)  iWb = i;
        else if (s == 524288)   { if (n524 < 2) i524[n524++] = i; }
        else if (s == 512)      { if (n512 < 2) i512[n512++] = i; }
    }
    bool alpha = (iQ >= 0 && iV >= 0 && iQ < iV);
    int iWv = alpha ? i524[1] : i524[0];
    int iWq = alpha ? i524[0] : i524[1];
    int ihv = alpha ? i512[1] : i512[0];
    int ihq = alpha ? i512[0] : i512[1];

    const float* V   = (const float*)d_in[iV];
    const float* Q   = (const float*)d_in[iQ];
    const void*  Qlen= d_in[iLen];
    const float* Wb  = (const float*)d_in[iWb];
    const float* Wv  = (const float*)d_in[iWv];
    const float* Wq  = (const float*)d_in[iWq];
    const float* whv = (const float*)d_in[ihv];
    const float* whq = (const float*)d_in[ihq];

    void *pVt, *pWb, *pWv, *pWq, *pWbVt, *pQbf, *pC, *pWvV2, *pWqQt, *pHv, *pHq, *pwhv, *pwhq;
    cudaGetSymbolAddress(&pVt,   g_Vt);
    cudaGetSymbolAddress(&pWb,   g_Wb);
    cudaGetSymbolAddress(&pWv,   g_Wv);
    cudaGetSymbolAddress(&pWq,   g_Wq);
    cudaGetSymbolAddress(&pWbVt, g_WbVt);
    cudaGetSymbolAddress(&pQbf,  g_Qbf);
    cudaGetSymbolAddress(&pC,    g_C);
    cudaGetSymbolAddress(&pWvV2, g_WvV2);
    cudaGetSymbolAddress(&pWqQt, g_WqQt);
    cudaGetSymbolAddress(&pHv,   g_Hv);
    cudaGetSymbolAddress(&pHq,   g_Hq);
    cudaGetSymbolAddress(&pwhv,  g_whv);
    cudaGetSymbolAddress(&pwhq,  g_whq);

    float* outf = (float*)d_out;                    // __output__ is float32
    const long OFF_MAQ = (long)NB * NR;                 // 12544
    const long OFF_V   = OFF_MAQ + (long)NB * NL;       // 45312
    const long OFF_Q   = OFF_V + (long)NB * NH;         // 110848

    static cudaStream_t s1 = nullptr, s2 = nullptr;
    static cudaEvent_t eS, eQ, eVt, e3, e4, eC, eJ1;
    if (s1 == nullptr) {
        cudaStreamCreateWithFlags(&s1, cudaStreamNonBlocking);
        cudaStreamCreateWithFlags(&s2, cudaStreamNonBlocking);
        cudaEventCreateWithFlags(&eS,  cudaEventDisableTiming);
        cudaEventCreateWithFlags(&eQ,  cudaEventDisableTiming);
        cudaEventCreateWithFlags(&eVt, cudaEventDisableTiming);
        cudaEventCreateWithFlags(&e3,  cudaEventDisableTiming);
        cudaEventCreateWithFlags(&e4,  cudaEventDisableTiming);
        cudaEventCreateWithFlags(&eC,  cudaEventDisableTiming);
        cudaEventCreateWithFlags(&eJ1, cudaEventDisableTiming);
    }
    cudaStream_t s0 = 0;

    // ---- fork -------------------------------------------------------------
    k_zero_f32<<<512, 256, 0, s0>>>(outf, (long)out_size);
    cudaEventRecord(eS, s0);
    cudaStreamWaitEvent(s1, eS, 0);
    cudaStreamWaitEvent(s2, eS, 0);

    // ---- s0: V path -> G1 -> G2 -> G5 -> a_v -> v ---------------------------
    k_convV<<<dim3(7, 32, NB), dim3(32, 8), 0, s0>>>(V);
    cudaEventRecord(eVt, s0);
    k_f32_to_bf16_v4<<<1024, 256, 0, s0>>>((const float4*)Wb, (uint2*)pWb, (long)NH * NH / 4);
    // G1 (concat): M = 12544 = 49*256 exact
    k_fgemm<0,0><<<dim3(8, 49, 1), GTHREADS, 0, s0>>>(
        (const __nv_bfloat16*)pVt, NH, 0,
        (const __nv_bfloat16*)pWb, NH, 0,
        (__nv_bfloat16*)pWbVt, NH, 0,
        nullptr, 0, 0, NBR, NH, NH);

    // ---- s1: Q path -> G4 ---------------------------------------------------
    k_f32_to_bf16_v4<<<8192, 256, 0, s1>>>((const float4*)Q, (uint2*)pQbf, (long)NB * NL * NH / 4);
    cudaEventRecord(eQ, s1);
    k_f32_to_bf16_v4<<<512, 256, 0, s1>>>((const float4*)Wq, (uint2*)pWq, (long)NK * NH / 4);
    k_len<<<1, 64, 0, s1>>>(Qlen);
    k_fgemm<0,0><<<dim3(4, 2, NB), GTHREADS, 0, s1>>>(
        (const __nv_bfloat16*)pWq, NH, 0,
        (const __nv_bfloat16*)pQbf, NH, (long)NL * NH,
        (__nv_bfloat16*)pWqQt, NL, (long)NK * NL,
        nullptr, 0, 0, NK, NL, NH);
    cudaEventRecord(e4, s1);

    // ---- s2: Wv path -> G3 --------------------------------------------------
    k_f32_to_bf16_v4<<<512, 256, 0, s2>>>((const float4*)Wv, (uint2*)pWv, (long)NK * NH / 4);
    k_round_w<<<2, 256, 0, s2>>>(whv, (float*)pwhv, NK);
    k_round_w<<<2, 256, 0, s2>>>(whq, (float*)pwhq, NK);
    cudaStreamWaitEvent(s2, eVt, 0);
    k_fgemm<0,0><<<dim3(98, 2, 1), GTHREADS, 0, s2>>>(
        (const __nv_bfloat16*)pWv, NH, 0,
        (const __nv_bfloat16*)pVt, NH, 0,
        (__nv_bfloat16*)pWvV2, NBR, 0,
        nullptr, 0, 0, NK, NBR, NH);
    cudaEventRecord(e3, s2);

    // ---- s0: G2 (needs Qbf) --------------------------------------------------
    cudaStreamWaitEvent(s0, eQ, 0);
    k_fgemm<0,0><<<dim3(2, 2, NB), GTHREADS, 0, s0>>>(
        (const __nv_bfloat16*)pQbf, NH, (long)NL * NH,
        (const __nv_bfloat16*)pWbVt, NH, (long)NR * NH,
        (__nv_bfloat16*)pC, NR, (long)NL * NR,
        nullptr, 0, 0, NL, NR, NH);
    cudaEventRecord(eC, s0);

    // ---- s0: G5 -> a_v -> v (needs WvV2, WqQt) ------------------------------
    cudaStreamWaitEvent(s0, e3, 0);
    cudaStreamWaitEvent(s0, e4, 0);
    k_fgemm<1,1><<<dim3(2, 2, NB), GTHREADS, 0, s0>>>(
        (const __nv_bfloat16*)pWqQt, NL, (long)NK * NL,
        (const __nv_bfloat16*)pC, NR, (long)NL * NR,
        (__nv_bfloat16*)pHv, NR, (long)NK * NR,
        (const __nv_bfloat16*)pWvV2, NBR, (long)NR,
        NK, NR, NL);
    k_sv_softmax<<<NB, 256, 0, s0>>>(outf);
    k_v<<<dim3(4, NB), 256, 0, s0>>>(outf + OFF_V);

    // ---- s1: G6 -> masked_a_q -> q (needs WvV2, C) ---------------------------
    cudaStreamWaitEvent(s1, e3, 0);
    cudaStreamWaitEvent(s1, eC, 0);
    k_fgemm<1,0><<<dim3(4, 2, NB), GTHREADS, 0, s1>>>(
        (const __nv_bfloat16*)pWvV2, NBR, (long)NR,
        (const __nv_bfloat16*)pC, NR, (long)NL * NR,
        (__nv_bfloat16*)pHq, NL, (long)NK * NL,
        (const __nv_bfloat16*)pWqQt, NL, (long)NK * NL,
        NK, NL, NR);
    k_sq_softmax<<<NB, 512, 0, s1>>>(outf + OFF_MAQ);
    k_q<<<dim3(4, NB), 256, 0, s1>>>(outf + OFF_Q);
    cudaEventRecord(eJ1, s1);

    // ---- join ---------------------------------------------------------------
    cudaStreamWaitEvent(s0, eJ1, 0);
}

// round 16
// speedup vs baseline: 1.0113x; 1.0113x over previous
#include <cuda_runtime.h>
#include <cuda_bf16.h>
#include <stdint.h>
#include <math.h>

// Problem constants
#define NB 64
#define NH 1024
#define NR 196
#define NL 512
#define NK 512
#define NBR (NB * NR)   // 12544 = 49 * 256 (exact M tiling!)

// ---------------- scratch (device globals; no allocation allowed) ----------
__device__ __nv_bfloat16 g_Vt   [(size_t)NB*NR*NH];
__device__ __nv_bfloat16 g_Qbf  [(size_t)NB*NL*NH];
__device__ __nv_bfloat16 g_Wb   [(size_t)NH*NH];
__device__ __nv_bfloat16 g_Wv   [(size_t)NK*NH];
__device__ __nv_bfloat16 g_Wq   [(size_t)NK*NH];
__device__ float         g_whv  [NK];
__device__ float         g_whq  [NK];
__device__ __nv_bfloat16 g_WbVt [(size_t)NBR*NH];      // [B*R][H]
__device__ __nv_bfloat16 g_C    [(size_t)NB*NL*NR];    // [B][L][R]
__device__ __nv_bfloat16 g_WvV2 [(size_t)NK*NBR];      // [K][B*R]  (ld = 12544)
__device__ __nv_bfloat16 g_WqQt [(size_t)NB*NK*NL];    // [B][K][L]
__device__ __nv_bfloat16 g_Hv   [(size_t)NB*NK*NR];    // [B][K][R]
__device__ __nv_bfloat16 g_Hq   [(size_t)NB*NK*NL];    // [B][K][L]
__device__ __nv_bfloat16 g_av   [NB*NR];
__device__ __nv_bfloat16 g_maq  [NB*NL];
__device__ int           g_len  [NB];

// ---------------- small helpers --------------------------------------------
__device__ __forceinline__ float rnd_bf(float x) {
    return __bfloat162float(__float2bfloat16(x));
}

__device__ __forceinline__ float blk_max(float v, float* red, int tid, int nt) {
    red[tid] = v; __syncthreads();
    for (int o = nt >> 1; o > 0; o >>= 1) {
        if (tid < o) red[tid] = fmaxf(red[tid], red[tid + o]);
        __syncthreads();
    }
    float r = red[0]; __syncthreads();
    return r;
}
__device__ __forceinline__ float blk_sum(float v, float* red, int tid, int nt) {
    red[tid] = v; __syncthreads();
    for (int o = nt >> 1; o > 0; o >>= 1) {
        if (tid < o) red[tid] += red[tid + o];
        __syncthreads();
    }
    float r = red[0]; __syncthreads();
    return r;
}

// ---------------- conversions ----------------------------------------------
__global__ void k_zero_f32(float* __restrict__ dst, long n) {
    long i = (long)blockIdx.x * blockDim.x + threadIdx.x;
    long st = (long)gridDim.x * blockDim.x;
    for (; i < n; i += st) dst[i] = 0.f;
}

__global__ void k_f32_to_bf16_v4(const float4* __restrict__ src,
                                 uint2* __restrict__ dst, long n4) {
    long i = (long)blockIdx.x * blockDim.x + threadIdx.x;
    long st = (long)gridDim.x * blockDim.x;
    for (; i < n4; i += st) {
        float4 v = src[i];
        __nv_bfloat16 b0 = __float2bfloat16(v.x), b1 = __float2bfloat16(v.y);
        __nv_bfloat16 b2 = __float2bfloat16(v.z), b3 = __float2bfloat16(v.w);
        uint2 o;
        o.x = (uint32_t)*reinterpret_cast<uint16_t*>(&b0) |
              ((uint32_t)*reinterpret_cast<uint16_t*>(&b1) << 16);
        o.y = (uint32_t)*reinterpret_cast<uint16_t*>(&b2) |
              ((uint32_t)*reinterpret_cast<uint16_t*>(&b3) << 16);
        dst[i] = o;
    }
}

__global__ void k_round_w(const float* __restrict__ src, float* __restrict__ dst, int n) {
    int i = blockIdx.x * blockDim.x + threadIdx.x;
    if (i < n) dst[i] = rnd_bf(src[i]);
}

// convert V [B,H,R] f32 -> transposed bf16 g_Vt [B,R,H]
__global__ void k_convV(const float* __restrict__ V) {
    __shared__ float tile[32][33];
    int b = blockIdx.z;
    int r0 = blockIdx.x * 32, h0 = blockIdx.y * 32;
    int tx = threadIdx.x, ty = threadIdx.y;
    const float* Vb = V + (size_t)b * NH * NR;
#pragma unroll
    for (int i = 0; i < 4; i++) {
        int h = h0 + ty + i * 8, r = r0 + tx;
        float v = 0.f;
        if (h < NH && r < NR) v = Vb[(size_t)h * NR + r];
        tile[ty + i * 8][tx] = v;
    }
    __syncthreads();
#pragma unroll
    for (int i = 0; i < 4; i++) {
        int r = r0 + ty + i * 8, h = h0 + tx;
        if (r < NR && h < NH)
            g_Vt[(size_t)b * NR * NH + (size_t)r * NH + h] = __float2bfloat16(tile[tx][ty + i * 8]);
    }
}

// normalize Q_lengths (handles both int32 and int64 storage)
__global__ void k_len(const void* __restrict__ p) {
    const int* pi = (const int*)p;
    __shared__ int is64;
    if (threadIdx.x == 0) {
        int flag = 1;
        for (int i = 1; i < 64; i += 2)
            if (pi[i] != 0) { flag = 0; break; }
        is64 = flag;
    }
    __syncthreads();
    int i = threadIdx.x;
    if (i < NB) g_len[i] = is64 ? pi[2 * i] : pi[i];
}

// ---------------- fast SIMT GEMM (256x128 tile, templated GBK) --------------
// C[M,N] = A[M,K] * op(B), op = B[N,K]^T (BNN=0) or B[K,N] (BNN=1).
// Sequential ascending-k per output element, single f32 accumulator
// (FFMA2 = elementwise IEEE f32 FMA; bit-identical to scalar chains).
// Thread: 16 rows (8 M-pairs) x 8 cols {tx*4+0..3} U {64+tx*4+0..3}.
// Inner loop register-pipelines fragments (k+1 LDS issued before k's FMAs).
// EPI==0: C = bf16(acc)
// EPI==1: C = bf16(tanh(bf16(bf16(acc) + Add[M,N])))
#define GBM 256
#define GBN 128
#define GTHREADS 256

// load 8 consecutive bf16 P[row][col..col+7] (leading dim ld) into 4 uint32
__device__ __forceinline__ void ld8g(const __nv_bfloat16* __restrict__ P,
                                     int row, int col, int nrow, int ncol,
                                     int ld, uint32_t r[4]) {
    if (row < nrow && col + 8 <= ncol) {
        const uint2* p = reinterpret_cast<const uint2*>(P + (size_t)row * ld + col);
        uint2 a = p[0], b = p[1];
        r[0] = a.x; r[1] = a.y; r[2] = b.x; r[3] = b.y;
    } else {
        uint16_t t[8];
#pragma unroll
        for (int j = 0; j < 8; j++) {
            __nv_bfloat16 v = (row < nrow && col + j < ncol)
                              ? P[(size_t)row * ld + col + j] : __nv_bfloat16(0.f);
            t[j] = *reinterpret_cast<uint16_t*>(&v);
        }
#pragma unroll
        for (int j = 0; j < 4; j++) r[j] = (uint32_t)t[2 * j] | ((uint32_t)t[2 * j + 1] << 16);
    }
}

template<int EPI, int BNN, int GBKT>
__global__ __launch_bounds__(GTHREADS, 1) void k_fgemm(
    const __nv_bfloat16* __restrict__ A, int lda, long strA,
    const __nv_bfloat16* __restrict__ Bm, int ldb, long strB,
    __nv_bfloat16* __restrict__ C, int ldc, long strC,
    const __nv_bfloat16* __restrict__ Add, int ldadd, long strAdd,
    int M, int N, int Kd)
{
    constexpr int SA = GBKT / 8;      // A ld8g segments per thread
    constexpr int SB = GBKT / 16;     // B ld8g segments per thread
    __shared__ float As[GBKT][GBM];
    __shared__ float Bs[GBKT][GBN];

    int bz = blockIdx.z;
    A += (size_t)bz * strA;
    Bm += (size_t)bz * strB;
    C += (size_t)bz * strC;
    if (EPI) Add += (size_t)bz * strAdd;

    int m0 = blockIdx.y * GBM, n0 = blockIdx.x * GBN;
    int tid = threadIdx.x;
    int rowA = tid;                        // A loader: one row, GBKT k-cols
    int rowB = tid >> 1;                   // NT B loader: 0..127
    int cB = (tid & 1) * (GBKT / 2);       // NT B loader col offset
    int kkB = tid >> 4;                    // NN: k rows kkB + s*16
    int n8B = (tid & 15) * 8;              // NN
    int tx = tid & 15, ty = tid >> 4;      // 16x16 grid, 16x8 per thread

    uint64_t acc2[8][8];
#pragma unroll
    for (int p = 0; p < 8; p++)
#pragma unroll
        for (int j = 0; j < 8; j++) acc2[p][j] = 0ull;

    int nk = (Kd + GBKT - 1) / GBKT;
    uint32_t ra[SA][4], rb[SB][4];

    auto prefetch = [&](int gk) {
#pragma unroll
        for (int s = 0; s < SA; s++)
            ld8g(A, m0 + rowA, gk + s * 8, M, Kd, lda, ra[s]);
        if (BNN) {
#pragma unroll
            for (int s = 0; s < SB; s++)
                ld8g(Bm, gk + kkB + s * 16, n0 + n8B, Kd, N, ldb, rb[s]);
        } else {
#pragma unroll
            for (int s = 0; s < SB; s++)
                ld8g(Bm, n0 + rowB, gk + cB + s * 8, N, Kd, ldb, rb[s]);
        }
    };

    prefetch(0);

    // fragment double buffers (register pipeline)
    uint64_t a2b[2][8];
    float bvb[2][8];

    auto ldfrag = [&](int k, int buf) {
        const ulonglong2* pa = reinterpret_cast<const ulonglong2*>(&As[k][ty * 16]);
        ulonglong2 aa = pa[0], ab = pa[1], ac = pa[2], ad = pa[3];
        a2b[buf][0] = aa.x; a2b[buf][1] = aa.y;
        a2b[buf][2] = ab.x; a2b[buf][3] = ab.y;
        a2b[buf][4] = ac.x; a2b[buf][5] = ac.y;
        a2b[buf][6] = ad.x; a2b[buf][7] = ad.y;
        float4 b0 = *reinterpret_cast<const float4*>(&Bs[k][tx * 4]);
        float4 b1 = *reinterpret_cast<const float4*>(&Bs[k][64 + tx * 4]);
        bvb[buf][0] = b0.x; bvb[buf][1] = b0.y; bvb[buf][2] = b0.z; bvb[buf][3] = b0.w;
        bvb[buf][4] = b1.x; bvb[buf][5] = b1.y; bvb[buf][6] = b1.z; bvb[buf][7] = b1.w;
    };

    for (int kt = 0; kt < nk; ++kt) {
        // deposit prefetched tile (bf16->f32 exact bit shift)
#pragma unroll
        for (int s = 0; s < SA; s++)
#pragma unroll
            for (int j = 0; j < 4; j++) {
                As[s * 8 + 2 * j][rowA]     = __uint_as_float(ra[s][j] << 16);
                As[s * 8 + 2 * j + 1][rowA] = __uint_as_float(ra[s][j] & 0xffff0000u);
            }
        if (BNN) {
#pragma unroll
            for (int s = 0; s < SB; s++)
#pragma unroll
                for (int j = 0; j < 4; j++) {
                    float2 w;
                    w.x = __uint_as_float(rb[s][j] << 16);
                    w.y = __uint_as_float(rb[s][j] & 0xffff0000u);
                    *reinterpret_cast<float2*>(&Bs[kkB + s * 16][n8B + 2 * j]) = w;
                }
        } else {
#pragma unroll
            for (int s = 0; s < SB; s++)
#pragma unroll
                for (int j = 0; j < 4; j++) {
                    Bs[cB + s * 8 + 2 * j][rowB]     = __uint_as_float(rb[s][j] << 16);
                    Bs[cB + s * 8 + 2 * j + 1][rowB] = __uint_as_float(rb[s][j] & 0xffff0000u);
                }
        }
        __syncthreads();

        if (kt + 1 < nk) prefetch((kt + 1) * GBKT);

        ldfrag(0, 0);
#pragma unroll
        for (int k = 0; k < GBKT; k++) {
            int cur = k & 1;
            if (k + 1 < GBKT) ldfrag(k + 1, cur ^ 1);
            uint64_t b2[8];
#pragma unroll
            for (int j = 0; j < 8; j++)
                asm("mov.b64 %0, {%1, %1};" : "=l"(b2[j]) : "f"(bvb[cur][j]));
#pragma unroll
            for (int p = 0; p < 8; p++)
#pragma unroll
                for (int j = 0; j < 8; j++)
                    asm("fma.rn.f32x2 %0, %1, %2, %0;"
                        : "+l"(acc2[p][j]) : "l"(a2b[cur][p]), "l"(b2[j]));
        }
        __syncthreads();
    }

    // epilogue: 16 rows (8 pairs) x two 4-col groups
#pragma unroll
    for (int p = 0; p < 8; p++) {
#pragma unroll
        for (int half = 0; half < 2; half++) {
            int r = m0 + ty * 16 + 2 * p + half;
            if (r >= M) continue;
#pragma unroll
            for (int g = 0; g < 2; g++) {
                int c0 = n0 + g * 64 + tx * 4;
                float accv[4];
#pragma unroll
                for (int j = 0; j < 4; j++) {
                    uint64_t v = acc2[p][g * 4 + j];
                    accv[j] = __uint_as_float(half ? (uint32_t)(v >> 32) : (uint32_t)v);
                }
                uint16_t outp[4];
                if (EPI == 0) {
#pragma unroll
                    for (int j = 0; j < 4; j++) {
                        __nv_bfloat16 v = __float2bfloat16(accv[j]);
                        outp[j] = *reinterpret_cast<uint16_t*>(&v);
                    }
                } else {
                    float addv[4];
                    if (c0 + 4 <= N) {
                        uint2 a = *reinterpret_cast<const uint2*>(Add + (size_t)r * ldadd + c0);
                        addv[0] = __uint_as_float(a.x << 16);
                        addv[1] = __uint_as_float(a.x & 0xffff0000u);
                        addv[2] = __uint_as_float(a.y << 16);
                        addv[3] = __uint_as_float(a.y & 0xffff0000u);
                    } else {
#pragma unroll
                        for (int j = 0; j < 4; j++)
                            addv[j] = (c0 + j < N)
                                      ? __bfloat162float(Add[(size_t)r * ldadd + c0 + j]) : 0.f;
                    }
#pragma unroll
                    for (int j = 0; j < 4; j++) {
                        float s = rnd_bf(accv[j]) + addv[j];
                        __nv_bfloat16 v = __float2bfloat16(tanhf(rnd_bf(s)));
                        outp[j] = *reinterpret_cast<uint16_t*>(&v);
                    }
                }
                if (c0 + 4 <= N) {
                    uint2 w;
                    w.x = (uint32_t)outp[0] | ((uint32_t)outp[1] << 16);
                    w.y = (uint32_t)outp[2] | ((uint32_t)outp[3] << 16);
                    *reinterpret_cast<uint2*>(C + (size_t)r * ldc + c0) = w;
                } else {
#pragma unroll
                    for (int j = 0; j < 4; j++)
                        if (c0 + j < N)
                            *reinterpret_cast<uint16_t*>(C + (size_t)r * ldc + c0 + j) = outp[j];
                }
            }
        }
    }
}

// ---------------- s_v reduce + bf16-emulated softmax (a_v) -> f32 out -------
__global__ void k_sv_softmax(float* __restrict__ out) {
    int b = blockIdx.x;
    __shared__ float wsm[NK];
    __shared__ float red[256];
    int tid = threadIdx.x;
    for (int i = tid; i < NK; i += 256) wsm[i] = g_whv[i];
    __syncthreads();
    const __nv_bfloat16* Hv = g_Hv + (size_t)b * NK * NR;
    float s = -INFINITY;
    int r = tid;
    if (r < NR) {
        float acc = 0.f;
        for (int k = 0; k < NK; k++)
            acc = fmaf(wsm[k], __bfloat162float(Hv[(size_t)k * NR + r]), acc);
        s = rnd_bf(acc);
    }
    float mx = blk_max(s, red, tid, 256);
    float e = 0.f;
    if (r < NR) e = rnd_bf(expf(rnd_bf(s - mx)));
    float sum = rnd_bf(blk_sum(e, red, tid, 256));
    if (r < NR) {
        __nv_bfloat16 av = __float2bfloat16(e / sum);
        g_av[b * NR + r] = av;
        out[b * NR + r] = __bfloat162float(av);
    }
}

// ---------------- s_q reduce + bf16 softmax + f32 masked softmax ------------
__global__ void k_sq_softmax(float* __restrict__ out) {
    int b = blockIdx.x;
    __shared__ float wsm[NK];
    __shared__ float red[512];
    int tid = threadIdx.x;  // 512
    for (int i = tid; i < NK; i += 512) wsm[i] = g_whq[i];
    __syncthreads();
    const __nv_bfloat16* Hq = g_Hq + (size_t)b * NK * NL;
    float acc = 0.f;
    for (int k = 0; k < NK; k++)
        acc = fmaf(wsm[k], __bfloat162float(Hq[(size_t)k * NL + tid]), acc);
    float s = rnd_bf(acc);
    float mx = blk_max(s, red, tid, 512);
    float e = rnd_bf(expf(rnd_bf(s - mx)));
    float sum = rnd_bf(blk_sum(e, red, tid, 512));
    float aqf = rnd_bf(e / sum);
    int len = g_len[b];
    float sc = (tid < len) ? aqf : -INFINITY;
    float m2 = blk_max(sc, red, tid, 512);
    float e2 = (tid < len) ? expf(sc - m2) : 0.f;
    float s2 = blk_sum(e2, red, tid, 512);
    __nv_bfloat16 mq = __float2bfloat16(e2 / s2);
    g_maq[b * NL + tid] = mq;
    out[b * NL + tid] = __bfloat162float(mq);
}

// ---------------- v = V @ a_v  (reads Vt coalesced, sequential r) -----------
__global__ void k_v(float* __restrict__ out) {
    int b = blockIdx.y;
    int h = blockIdx.x * 256 + threadIdx.x;
    __shared__ float av[NR];
    for (int i = threadIdx.x; i < NR; i += 256)
        av[i] = __bfloat162float(g_av[b * NR + i]);
    __syncthreads();
    const __nv_bfloat16* Vtb = g_Vt + (size_t)b * NR * NH;
    float acc = 0.f;
    for (int r = 0; r < NR; r++)
        acc = fmaf(av[r], __bfloat162float(Vtb[(size_t)r * NH + h]), acc);
    out[b * NH + h] = rnd_bf(acc);
}

// ---------------- q = Q^T @ masked_a_q ---------------------------------------
__global__ void k_q(float* __restrict__ out) {
    int b = blockIdx.y;
    int h = blockIdx.x * 256 + threadIdx.x;
    __shared__ float aq[NL];
    for (int i = threadIdx.x; i < NL; i += 256)
        aq[i] = __bfloat162float(g_maq[b * NL + i]);
    __syncthreads();
    const __nv_bfloat16* Qb = g_Qbf + (size_t)b * NL * NH;
    float acc = 0.f;
    for (int l = 0; l < NL; l++)
        acc = fmaf(aq[l], __bfloat162float(Qb[(size_t)l * NH + h]), acc);
    out[b * NH + h] = rnd_bf(acc);
}

// ---------------- host ---------------------------------------------------------
extern "C" void kernel_launch(void* const* d_in, const int* in_sizes, int n_in,
                              void* d_out, int out_size) {
    // identify inputs by element count
    int iV = -1, iQ = -1, iLen = -1, iWb = -1;
    int i524[2] = {-1, -1}, n524 = 0;
    int i512[2] = {-1, -1}, n512 = 0;
    for (int i = 0; i < n_in; i++) {
        long s = in_sizes[i];
        if      (s == 12845056) iV = i;
        else if (s == 33554432) iQ = i;
        else if (s == 64)       iLen = i;
        else if (s == 1048576)  iWb = i;
        else if (s == 524288)   { if (n524 < 2) i524[n524++] = i; }
        else if (s == 512)      { if (n512 < 2) i512[n512++] = i; }
    }
    bool alpha = (iQ >= 0 && iV >= 0 && iQ < iV);
    int iWv = alpha ? i524[1] : i524[0];
    int iWq = alpha ? i524[0] : i524[1];
    int ihv = alpha ? i512[1] : i512[0];
    int ihq = alpha ? i512[0] : i512[1];

    const float* V   = (const float*)d_in[iV];
    const float* Q   = (const float*)d_in[iQ];
    const void*  Qlen= d_in[iLen];
    const float* Wb  = (const float*)d_in[iWb];
    const float* Wv  = (const float*)d_in[iWv];
    const float* Wq  = (const float*)d_in[iWq];
    const float* whv = (const float*)d_in[ihv];
    const float* whq = (const float*)d_in[ihq];

    void *pVt, *pWb, *pWv, *pWq, *pWbVt, *pQbf, *pC, *pWvV2, *pWqQt, *pHv, *pHq, *pwhv, *pwhq;
    cudaGetSymbolAddress(&pVt,   g_Vt);
    cudaGetSymbolAddress(&pWb,   g_Wb);
    cudaGetSymbolAddress(&pWv,   g_Wv);
    cudaGetSymbolAddress(&pWq,   g_Wq);
    cudaGetSymbolAddress(&pWbVt, g_WbVt);
    cudaGetSymbolAddress(&pQbf,  g_Qbf);
    cudaGetSymbolAddress(&pC,    g_C);
    cudaGetSymbolAddress(&pWvV2, g_WvV2);
    cudaGetSymbolAddress(&pWqQt, g_WqQt);
    cudaGetSymbolAddress(&pHv,   g_Hv);
    cudaGetSymbolAddress(&pHq,   g_Hq);
    cudaGetSymbolAddress(&pwhv,  g_whv);
    cudaGetSymbolAddress(&pwhq,  g_whq);

    float* outf = (float*)d_out;                    // __output__ is float32
    const long OFF_MAQ = (long)NB * NR;                 // 12544
    const long OFF_V   = OFF_MAQ + (long)NB * NL;       // 45312
    const long OFF_Q   = OFF_V + (long)NB * NH;         // 110848

    static cudaStream_t s1 = nullptr, s2 = nullptr;
    static cudaEvent_t eS, eQ, eVt, e3, e4, eC, eJ1;
    if (s1 == nullptr) {
        cudaStreamCreateWithFlags(&s1, cudaStreamNonBlocking);
        cudaStreamCreateWithFlags(&s2, cudaStreamNonBlocking);
        cudaEventCreateWithFlags(&eS,  cudaEventDisableTiming);
        cudaEventCreateWithFlags(&eQ,  cudaEventDisableTiming);
        cudaEventCreateWithFlags(&eVt, cudaEventDisableTiming);
        cudaEventCreateWithFlags(&e3,  cudaEventDisableTiming);
        cudaEventCreateWithFlags(&e4,  cudaEventDisableTiming);
        cudaEventCreateWithFlags(&eC,  cudaEventDisableTiming);
        cudaEventCreateWithFlags(&eJ1, cudaEventDisableTiming);
    }
    cudaStream_t s0 = 0;

    // ---- fork -------------------------------------------------------------
    k_zero_f32<<<512, 256, 0, s0>>>(outf, (long)out_size);
    cudaEventRecord(eS, s0);
    cudaStreamWaitEvent(s1, eS, 0);
    cudaStreamWaitEvent(s2, eS, 0);

    // ---- s0: V path -> G1 -> G2 -> G5 -> a_v -> v ---------------------------
    k_convV<<<dim3(7, 32, NB), dim3(32, 8), 0, s0>>>(V);
    cudaEventRecord(eVt, s0);
    k_f32_to_bf16_v4<<<1024, 256, 0, s0>>>((const float4*)Wb, (uint2*)pWb, (long)NH * NH / 4);
    // G1 (concat): M = 12544 = 49*256 exact, K=1024
    k_fgemm<0,0,32><<<dim3(8, 49, 1), GTHREADS, 0, s0>>>(
        (const __nv_bfloat16*)pVt, NH, 0,
        (const __nv_bfloat16*)pWb, NH, 0,
        (__nv_bfloat16*)pWbVt, NH, 0,
        nullptr, 0, 0, NBR, NH, NH);

    // ---- s1: Q path -> G4 ---------------------------------------------------
    k_f32_to_bf16_v4<<<8192, 256, 0, s1>>>((const float4*)Q, (uint2*)pQbf, (long)NB * NL * NH / 4);
    cudaEventRecord(eQ, s1);
    k_f32_to_bf16_v4<<<512, 256, 0, s1>>>((const float4*)Wq, (uint2*)pWq, (long)NK * NH / 4);
    k_len<<<1, 64, 0, s1>>>(Qlen);
    k_fgemm<0,0,32><<<dim3(4, 2, NB), GTHREADS, 0, s1>>>(
        (const __nv_bfloat16*)pWq, NH, 0,
        (const __nv_bfloat16*)pQbf, NH, (long)NL * NH,
        (__nv_bfloat16*)pWqQt, NL, (long)NK * NL,
        nullptr, 0, 0, NK, NL, NH);
    cudaEventRecord(e4, s1);

    // ---- s2: Wv path -> G3 --------------------------------------------------
    k_f32_to_bf16_v4<<<512, 256, 0, s2>>>((const float4*)Wv, (uint2*)pWv, (long)NK * NH / 4);
    k_round_w<<<2, 256, 0, s2>>>(whv, (float*)pwhv, NK);
    k_round_w<<<2, 256, 0, s2>>>(whq, (float*)pwhq, NK);
    cudaStreamWaitEvent(s2, eVt, 0);
    k_fgemm<0,0,32><<<dim3(98, 2, 1), GTHREADS, 0, s2>>>(
        (const __nv_bfloat16*)pWv, NH, 0,
        (const __nv_bfloat16*)pVt, NH, 0,
        (__nv_bfloat16*)pWvV2, NBR, 0,
        nullptr, 0, 0, NK, NBR, NH);
    cudaEventRecord(e3, s2);

    // ---- s0: G2 (needs Qbf), K=1024 ------------------------------------------
    cudaStreamWaitEvent(s0, eQ, 0);
    k_fgemm<0,0,32><<<dim3(2, 2, NB), GTHREADS, 0, s0>>>(
        (const __nv_bfloat16*)pQbf, NH, (long)NL * NH,
        (const __nv_bfloat16*)pWbVt, NH, (long)NR * NH,
        (__nv_bfloat16*)pC, NR, (long)NL * NR,
        nullptr, 0, 0, NL, NR, NH);
    cudaEventRecord(eC, s0);

    // ---- s0: G5 -> a_v -> v (needs WvV2, WqQt), K=512 -------------------------
    cudaStreamWaitEvent(s0, e3, 0);
    cudaStreamWaitEvent(s0, e4, 0);
    k_fgemm<1,1,32><<<dim3(2, 2, NB), GTHREADS, 0, s0>>>(
        (const __nv_bfloat16*)pWqQt, NL, (long)NK * NL,
        (const __nv_bfloat16*)pC, NR, (long)NL * NR,
        (__nv_bfloat16*)pHv, NR, (long)NK * NR,
        (const __nv_bfloat16*)pWvV2, NBR, (long)NR,
        NK, NR, NL);
    k_sv_softmax<<<NB, 256, 0, s0>>>(outf);
    k_v<<<dim3(4, NB), 256, 0, s0>>>(outf + OFF_V);

    // ---- s1: G6 -> masked_a_q -> q (needs WvV2, C), K=196 -> GBK16 ------------
    cudaStreamWaitEvent(s1, e3, 0);
    cudaStreamWaitEvent(s1, eC, 0);
    k_fgemm<1,0,16><<<dim3(4, 2, NB), GTHREADS, 0, s1>>>(
        (const __nv_bfloat16*)pWvV2, NBR, (long)NR,
        (const __nv_bfloat16*)pC, NR, (long)NL * NR,
        (__nv_bfloat16*)pHq, NL, (long)NK * NL,
        (const __nv_bfloat16*)pWqQt, NL, (long)NK * NL,
        NK, NL, NR);
    k_sq_softmax<<<NB, 512, 0, s1>>>(outf + OFF_MAQ);
    k_q<<<dim3(4, NB), 256, 0, s1>>>(outf + OFF_Q);
    cudaEventRecord(eJ1, s1);

    // ---- join ---------------------------------------------------------------
    cudaStreamWaitEvent(s0, eJ1, 0);
}